// round 11
// baseline (speedup 1.0000x reference)
#include <cuda_runtime.h>
#include <cuda_bf16.h>

#define TT 500
#define BB 1024
#define EE 26
#define HH 100
#define PP 80
#define DD 64

static const long long SM_N = (long long)(PP - 1) * BB * DD; // 5177344
static const long long TG_N = (long long)(PP - 1) * BB;      // 80896

// static device scratch (no allocation allowed)
__device__ float g_e0[TT * BB * HH];
__device__ float g_d0[PP * BB * HH];
__device__ float g_d1[PP * BB * HH];
__device__ float g_decin[PP * BB * EE];
__device__ float g_henc0[BB * HH];
__device__ float g_henc1[BB * HH];

__device__ __forceinline__ float sigf(float x) {
    return 1.0f / (1.0f + expf(-x));
}

// Persistent GRU layer. One CTA owns R=7 batch rows for all T steps.
// Mirrors the reference algebra: gi = x@WihT (+bih), gh = h@WhhT (+bhh),
// gates from (i_g + h_g), unfused elementwise combine.
// Smem: Wt[k][j] transposed weights; U[k][0..7] concatenated [x_t, h] rows.
// Last S hidden k-rows of Whh live in per-thread registers.
template <int KIN, int S>
__global__ void __launch_bounds__(128, 1)
gru_kernel(int T,
           const float* __restrict__ in,   // [T,B,KIN]
           const float* __restrict__ Wih,  // [300,KIN]
           const float* __restrict__ Whh,  // [300,100]
           const float* __restrict__ bih,
           const float* __restrict__ bhh,
           const float* __restrict__ h0,   // [B,100] or null (zeros)
           float* __restrict__ ys,         // [T,B,100] or null
           float* __restrict__ hT)         // [B,100] or null
{
    constexpr int H = HH, J = 3 * HH, B = BB, R = 7;
    constexpr int KTOT = KIN + H;
    constexpr int KS = KTOT - S;
    extern __shared__ float sm[];
    float* Wt = sm;            // KS * J
    float* U  = sm + KS * J;   // KTOT * 8

    const int tid = threadIdx.x;
    const int b0 = blockIdx.x * R;
    const int i = tid;
    const bool act = (tid < H);

    for (int idx = tid; idx < J * KIN; idx += 128) {
        int j = idx / KIN, k = idx - j * KIN;
        Wt[k * J + j] = Wih[idx];
    }
    for (int idx = tid; idx < J * H; idx += 128) {
        int j = idx / H, kh = idx - j * H;
        if (kh < H - S) Wt[(KIN + kh) * J + j] = Whh[idx];
    }
    float wsp[(S > 0 ? S : 1) * 3];
    if constexpr (S > 0) {
        if (act) {
#pragma unroll
            for (int s = 0; s < S; s++)
#pragma unroll
                for (int g = 0; g < 3; g++)
                    wsp[s * 3 + g] = Whh[(g * H + i) * H + (H - S + s)];
        }
    }
    // init hidden part of U
    for (int idx = tid; idx < H * 8; idx += 128) {
        int ih = idx >> 3, r = idx & 7;
        float v = 0.f;
        int b = b0 + r;
        if (h0 && r < R && b < B) v = h0[b * H + ih];
        U[(KIN + ih) * 8 + r] = v;
    }
    // stage input t=0
    for (int idx = tid; idx < KIN * 8; idx += 128) {
        int k = idx >> 3, r = idx & 7;
        int rr = (r < R) ? r : (R - 1);
        int b = b0 + rr; if (b >= B) b = B - 1;
        U[k * 8 + r] = in[(size_t)b * KIN + k];
    }
    // biases kept separate, applied after each dot (reference order)
    float bir = 0.f, biz = 0.f, bin_ = 0.f, bhr = 0.f, bhz = 0.f, bhn = 0.f;
    if (act) {
        bir = bih[i];         bhr = bhh[i];
        biz = bih[H + i];     bhz = bhh[H + i];
        bin_ = bih[2 * H + i]; bhn = bhh[2 * H + i];
    }
    __syncthreads();

    for (int t = 0; t < T; ++t) {
        // separate input-part and hidden-part accumulators (reference: gi, gh)
        float ir[R], iz[R], in_[R], hr[R], hz[R], hnacc[R], hn[R];
#pragma unroll
        for (int r = 0; r < R; r++) {
            ir[r]=0.f; iz[r]=0.f; in_[r]=0.f;
            hr[r]=0.f; hz[r]=0.f; hnacc[r]=0.f;
        }

        if (act) {
#pragma unroll 4
            for (int k = 0; k < KIN; k++) {
                float4 a = *(const float4*)&U[k * 8];
                float4 b4 = *(const float4*)&U[k * 8 + 4];
                float u7[7] = {a.x, a.y, a.z, a.w, b4.x, b4.y, b4.z};
                float wr = Wt[k * J + i];
                float wz = Wt[k * J + H + i];
                float wn = Wt[k * J + 2 * H + i];
#pragma unroll
                for (int r = 0; r < R; r++) {
                    ir[r] = fmaf(u7[r], wr, ir[r]);
                    iz[r] = fmaf(u7[r], wz, iz[r]);
                    in_[r] = fmaf(u7[r], wn, in_[r]);
                }
            }
#pragma unroll 4
            for (int kh = 0; kh < H - S; kh++) {
                int k = KIN + kh;
                float4 a = *(const float4*)&U[k * 8];
                float4 b4 = *(const float4*)&U[k * 8 + 4];
                float u7[7] = {a.x, a.y, a.z, a.w, b4.x, b4.y, b4.z};
                float wr = Wt[k * J + i];
                float wz = Wt[k * J + H + i];
                float wn = Wt[k * J + 2 * H + i];
#pragma unroll
                for (int r = 0; r < R; r++) {
                    hr[r] = fmaf(u7[r], wr, hr[r]);
                    hz[r] = fmaf(u7[r], wz, hz[r]);
                    hnacc[r] = fmaf(u7[r], wn, hnacc[r]);
                }
            }
            if constexpr (S > 0) {
#pragma unroll
                for (int s = 0; s < S; s++) {
                    int k = KIN + H - S + s;
                    float4 a = *(const float4*)&U[k * 8];
                    float4 b4 = *(const float4*)&U[k * 8 + 4];
                    float u7[7] = {a.x, a.y, a.z, a.w, b4.x, b4.y, b4.z};
#pragma unroll
                    for (int r = 0; r < R; r++) {
                        hr[r] = fmaf(u7[r], wsp[s*3+0], hr[r]);
                        hz[r] = fmaf(u7[r], wsp[s*3+1], hz[r]);
                        hnacc[r] = fmaf(u7[r], wsp[s*3+2], hnacc[r]);
                    }
                }
            }
#pragma unroll
            for (int r = 0; r < R; r++) {
                float hold = U[(KIN + i) * 8 + r];
                // reference: gi = dot + bih; gh = dot + bhh; gate = f(i_g + h_g)
                float gir = __fadd_rn(ir[r], bir);
                float ghr = __fadd_rn(hr[r], bhr);
                float giz = __fadd_rn(iz[r], biz);
                float ghz = __fadd_rn(hz[r], bhz);
                float gin = __fadd_rn(in_[r], bin_);
                float ghn = __fadd_rn(hnacc[r], bhn);
                float rr = sigf(__fadd_rn(gir, ghr));
                float zz = sigf(__fadd_rn(giz, ghz));
                // n = tanh(i_n + r * h_n), unfused
                float nn = tanhf(__fadd_rn(gin, __fmul_rn(rr, ghn)));
                // h_new = (1-z)*n + z*h, unfused
                float t1 = __fmul_rn(__fadd_rn(1.0f, -zz), nn);
                float t2 = __fmul_rn(zz, hold);
                hn[r] = __fadd_rn(t1, t2);
            }
        }
        __syncthreads();
        if (act) {
#pragma unroll
            for (int r = 0; r < R; r++) {
                U[(KIN + i) * 8 + r] = hn[r];
                int b = b0 + r;
                if (b < B) {
                    if (ys) ys[((size_t)t * B + b) * H + i] = hn[r];
                    if (hT && t == T - 1) hT[(size_t)b * H + i] = hn[r];
                }
            }
        }
        if (t + 1 < T) {
            const float* inp = in + (size_t)(t + 1) * B * KIN;
            for (int idx = tid; idx < KIN * 8; idx += 128) {
                int k = idx >> 3, r = idx & 7;
                int rr = (r < R) ? r : (R - 1);
                int b = b0 + rr; if (b >= B) b = B - 1;
                U[k * 8 + r] = inp[(size_t)b * KIN + k];
            }
        }
        __syncthreads();
    }
}

// target is int32 on device (harness downcasts int64 inputs to int32).
__global__ void gather_emb_kernel(const int* __restrict__ target,
                                  const float* __restrict__ emb,
                                  float* __restrict__ out)
{
    int idx = blockIdx.x * blockDim.x + threadIdx.x;
    const int N = PP * BB * EE;
    if (idx >= N) return;
    int row = idx / EE;
    int e = idx - row * EE;
    int t = __ldg(&target[row]);
    t = min(max(t, 0), DD - 1);   // crash-insurance clamp
    out[idx] = __ldg(&emb[t * EE + e]);
}

// logits [79,1024,64] + first-max argmax + target_cal copy.
// One warp per row; lane computes columns (lane, lane+32).
// k-ordered FMA dot from 0, bias added at the end (reference op order).
__global__ void __launch_bounds__(256)
logits_kernel(const float* __restrict__ d1, const float* __restrict__ W,
              const float* __restrict__ bias, const int* __restrict__ tgt,
              float* __restrict__ out_sm, float* __restrict__ out_tc,
              float* __restrict__ out_am)
{
    const int ROWS = (PP - 1) * BB;
    __shared__ float WT[HH * DD]; // WT[k*64+j] = W[j*100+k]
    int tid = threadIdx.x;
    for (int idx = tid; idx < HH * DD; idx += 256) {
        int k = idx >> 6, j = idx & 63;
        WT[idx] = W[j * HH + k];
    }
    __syncthreads();
    int warp = tid >> 5, lane = tid & 31;
    float b0 = __ldg(&bias[lane]), b1 = __ldg(&bias[lane + 32]);
    for (int row = blockIdx.x * 8 + warp; row < ROWS; row += gridDim.x * 8) {
        const float* h = d1 + (size_t)row * HH;
        float a0 = 0.f, a1 = 0.f;
#pragma unroll 4
        for (int k = 0; k < HH; k++) {
            float hk = __ldg(&h[k]);
            a0 = fmaf(hk, WT[k * 64 + lane], a0);
            a1 = fmaf(hk, WT[k * 64 + lane + 32], a1);
        }
        a0 = __fadd_rn(a0, b0);
        a1 = __fadd_rn(a1, b1);
        if (out_sm) {
            out_sm[(size_t)row * 64 + lane] = a0;
            out_sm[(size_t)row * 64 + lane + 32] = a1;
        }
        float v; int bi;
        if (a1 > a0) { v = a1; bi = lane + 32; } else { v = a0; bi = lane; }
#pragma unroll
        for (int off = 16; off > 0; off >>= 1) {
            float ov = __shfl_down_sync(0xFFFFFFFFu, v, off);
            int oi = __shfl_down_sync(0xFFFFFFFFu, bi, off);
            if (ov > v || (ov == v && oi < bi)) { v = ov; bi = oi; }
        }
        if (lane == 0) {
            if (out_am) out_am[row] = (float)bi;
            if (out_tc) out_tc[row] = (float)__ldg(&tgt[BB + row]);
        }
    }
}

extern "C" void kernel_launch(void* const* d_in, const int* in_sizes, int n_in,
                              void* d_out, int out_size)
{
    const float* x = (const float*)d_in[0];
    const int* target = (const int*)d_in[1];
    const float* emb = (const float*)d_in[2];
    const float* eW0 = (const float*)d_in[3];
    const float* eU0 = (const float*)d_in[4];
    const float* ebi0 = (const float*)d_in[5];
    const float* ebh0 = (const float*)d_in[6];
    const float* eW1 = (const float*)d_in[7];
    const float* eU1 = (const float*)d_in[8];
    const float* ebi1 = (const float*)d_in[9];
    const float* ebh1 = (const float*)d_in[10];
    const float* dW0 = (const float*)d_in[11];
    const float* dU0 = (const float*)d_in[12];
    const float* dbi0 = (const float*)d_in[13];
    const float* dbh0 = (const float*)d_in[14];
    const float* dW1 = (const float*)d_in[15];
    const float* dU1 = (const float*)d_in[16];
    const float* dbi1 = (const float*)d_in[17];
    const float* dbh1 = (const float*)d_in[18];
    const float* linW = (const float*)d_in[19];
    const float* linb = (const float*)d_in[20];

    float *e0, *d0, *d1, *decin, *h0, *h1;
    cudaGetSymbolAddress((void**)&e0, g_e0);
    cudaGetSymbolAddress((void**)&d0, g_d0);
    cudaGetSymbolAddress((void**)&d1, g_d1);
    cudaGetSymbolAddress((void**)&decin, g_decin);
    cudaGetSymbolAddress((void**)&h0, g_henc0);
    cudaGetSymbolAddress((void**)&h1, g_henc1);

    const int SMEM26 = (126 * 300 + 126 * 8) * 4;   // 155232
    const int SMEM100 = (188 * 300 + 200 * 8) * 4;  // 232000
    cudaFuncSetAttribute(gru_kernel<EE, 0>,
        cudaFuncAttributeMaxDynamicSharedMemorySize, SMEM26);
    cudaFuncSetAttribute(gru_kernel<HH, 12>,
        cudaFuncAttributeMaxDynamicSharedMemorySize, SMEM100);

    const int GRID = (BB + 6) / 7; // 147

    // encoder layer 0: x -> e0, hT -> g_henc0
    gru_kernel<EE, 0><<<GRID, 128, SMEM26>>>(TT, x, eW0, eU0, ebi0, ebh0,
                                             nullptr, e0, h0);
    // encoder layer 1: e0 -> (discard ys), hT -> g_henc1
    gru_kernel<HH, 12><<<GRID, 128, SMEM100>>>(TT, e0, eW1, eU1, ebi1, ebh1,
                                               nullptr, nullptr, h1);
    // decoder input gather
    {
        int N = PP * BB * EE;
        gather_emb_kernel<<<(N + 255) / 256, 256>>>(target, emb, decin);
    }
    // decoder layer 0: decin -> d0, h0 = g_henc0
    gru_kernel<EE, 0><<<GRID, 128, SMEM26>>>(PP, decin, dW0, dU0, dbi0, dbh0,
                                             h0, d0, nullptr);
    // decoder layer 1: d0 -> d1, h0 = g_henc1
    gru_kernel<HH, 12><<<GRID, 128, SMEM100>>>(PP, d0, dW1, dU1, dbi1, dbh1,
                                               h1, d1, nullptr);
    // epilogue: logits + argmax + target_cal, packed into d_out as float32
    {
        float* out = (float*)d_out;
        float* out_sm = (out_size >= (int)SM_N) ? out : nullptr;
        float* out_tc = (out_size >= (int)(SM_N + TG_N)) ? out + SM_N : nullptr;
        float* out_am = (out_size >= (int)(SM_N + 2 * TG_N)) ? out + SM_N + TG_N : nullptr;
        logits_kernel<<<1184, 256>>>(d1, linW, linb, target, out_sm, out_tc, out_am);
    }
}

// round 12
// speedup vs baseline: 1.1854x; 1.1854x over previous
#include <cuda_runtime.h>
#include <cuda_bf16.h>

#define TT 500
#define BB 1024
#define EE 26
#define HH 100
#define PP 80
#define DD 64

static const long long SM_N = (long long)(PP - 1) * BB * DD; // 5177344
static const long long TG_N = (long long)(PP - 1) * BB;      // 80896

// static device scratch (no allocation allowed)
__device__ float g_e0[TT * BB * HH];
__device__ float g_d0[PP * BB * HH];
__device__ float g_d1[PP * BB * HH];
__device__ float g_decin[PP * BB * EE];
__device__ float g_henc0[BB * HH];
__device__ float g_henc1[BB * HH];

__device__ __forceinline__ float sigf(float x) {
    return 1.0f / (1.0f + expf(-x));
}

// ---- packed f32x2 helpers (each half = independent IEEE op -> bitwise
// identical to scalar fmaf/__fadd_rn per lane) ----
__device__ __forceinline__ unsigned long long pack2(float w) {
    unsigned long long r;
    asm("mov.b64 %0, {%1, %1};" : "=l"(r) : "f"(w));
    return r;
}
__device__ __forceinline__ void fma2(unsigned long long& a,
                                     unsigned long long u,
                                     unsigned long long w) {
    asm("fma.rn.f32x2 %0, %1, %2, %0;" : "+l"(a) : "l"(u), "l"(w));
}
__device__ __forceinline__ unsigned long long add2(unsigned long long a,
                                                   unsigned long long b) {
    unsigned long long r;
    asm("add.rn.f32x2 %0, %1, %2;" : "=l"(r) : "l"(a), "l"(b));
    return r;
}
__device__ __forceinline__ void st2(float* p, unsigned long long v) {
    union { unsigned long long u; float2 f; } c;
    c.u = v;
    *(float2*)p = c.f;
}

// Persistent GRU layer, gate-unit ownership version.
// 320 threads; threads 0..299 each own one gate-row j of the 3H=300 outputs
// and accumulate input-part (gi) and hidden-part (gh) dots for R=8 batch rows
// using packed f32x2 FMAs (4 accumulators per part). Gate values (+bias, in
// reference order) go through smem G; combine phase (all 320 threads) applies
// sigmoid/tanh and the unfused reference combine. Arithmetic is bitwise
// identical to the R11 passing kernel: same ascending-k FMA chains per
// (gate-row, batch-row), same __fadd_rn/__fmul_rn order.
// Smem: Wt[k][j] (k < KIN+H-S), U[k][0..7], G[4][H][8].
// Last S hidden k-rows of Whh live in per-thread registers (ascending-k tail).
template <int KIN, int S>
__global__ void __launch_bounds__(320, 1)
gru_kernel(int T,
           const float* __restrict__ in,   // [T,B,KIN]
           const float* __restrict__ Wih,  // [300,KIN]
           const float* __restrict__ Whh,  // [300,100]
           const float* __restrict__ bih,
           const float* __restrict__ bhh,
           const float* __restrict__ h0,   // [B,100] or null (zeros)
           float* __restrict__ ys,         // [T,B,100] or null
           float* __restrict__ hT)         // [B,100] or null
{
    constexpr int H = HH, J = 3 * HH, B = BB, R = 8;
    constexpr int KTOT = KIN + H;
    constexpr int KS = KTOT - S;
    constexpr int NPF = (KIN * 8 + 319) / 320;   // prefetch regs
    extern __shared__ float sm[];
    float* Wt = sm;                 // KS * J
    float* U  = sm + KS * J;        // KTOT * 8
    float* G  = U + KTOT * 8;       // 4 * H * 8 = 3200 floats

    const int tid = threadIdx.x;
    const int b0 = blockIdx.x * R;
    const int j = tid;
    const bool dotact = (j < J);
    const int g = j / H;            // gate: 0=r, 1=z, 2=n
    const int iu = j - g * H;       // hidden unit

    // --- weight transpose into smem ---
    for (int idx = tid; idx < J * KIN; idx += 320) {
        int jj = idx / KIN, k = idx - jj * KIN;
        Wt[k * J + jj] = Wih[idx];
    }
    for (int idx = tid; idx < J * (H - S); idx += 320) {
        int jj = idx / (H - S), kh = idx - jj * (H - S);
        Wt[(KIN + kh) * J + jj] = Whh[jj * H + kh];
    }
    // --- spilled Whh tail (ascending-k) in registers ---
    float wsp[(S > 0 ? S : 1)];
    if constexpr (S > 0) {
        if (dotact) {
#pragma unroll
            for (int s = 0; s < S; s++)
                wsp[s] = Whh[j * H + (H - S) + s];
        }
    }
    // --- init hidden part of U ---
    for (int idx = tid; idx < H * 8; idx += 320) {
        int ih = idx >> 3, r = idx & 7;
        U[(KIN + ih) * 8 + r] = h0 ? h0[(size_t)(b0 + r) * H + ih] : 0.0f;
    }
    // --- stage x_0 (r-major mapping: coalesced LDG) ---
    for (int idx = tid; idx < KIN * 8; idx += 320) {
        int r = idx / KIN, k = idx - r * KIN;
        U[k * 8 + r] = in[(size_t)(b0 + r) * KIN + k];
    }
    float bi = 0.f, bh = 0.f;
    if (dotact) { bi = bih[j]; bh = bhh[j]; }
    __syncthreads();

    for (int t = 0; t < T; ++t) {
        // prefetch next step's input early (hidden under dot phase)
        float nx[NPF];
        if (t + 1 < T) {
            const float* inp = in + (size_t)(t + 1) * B * KIN;
#pragma unroll
            for (int p = 0; p < NPF; p++) {
                int idx = tid + p * 320;
                if (idx < KIN * 8) {
                    int r = idx / KIN, k = idx - r * KIN;
                    nx[p] = inp[(size_t)(b0 + r) * KIN + k];
                }
            }
        }

        if (dotact) {
            unsigned long long ai0 = 0, ai1 = 0, ai2 = 0, ai3 = 0;
            unsigned long long ah0 = 0, ah1 = 0, ah2 = 0, ah3 = 0;
            const float* wcol = Wt + j;
#pragma unroll 4
            for (int k = 0; k < KIN; k++) {
                unsigned long long w2 = pack2(wcol[k * J]);
                ulonglong2 uA = *(const ulonglong2*)&U[k * 8];
                ulonglong2 uB = *(const ulonglong2*)&U[k * 8 + 4];
                fma2(ai0, uA.x, w2); fma2(ai1, uA.y, w2);
                fma2(ai2, uB.x, w2); fma2(ai3, uB.y, w2);
            }
#pragma unroll 4
            for (int kh = 0; kh < H - S; kh++) {
                int k = KIN + kh;
                unsigned long long w2 = pack2(wcol[k * J]);
                ulonglong2 uA = *(const ulonglong2*)&U[k * 8];
                ulonglong2 uB = *(const ulonglong2*)&U[k * 8 + 4];
                fma2(ah0, uA.x, w2); fma2(ah1, uA.y, w2);
                fma2(ah2, uB.x, w2); fma2(ah3, uB.y, w2);
            }
            if constexpr (S > 0) {
#pragma unroll
                for (int s = 0; s < S; s++) {
                    int k = KIN + (H - S) + s;
                    unsigned long long w2 = pack2(wsp[s]);
                    ulonglong2 uA = *(const ulonglong2*)&U[k * 8];
                    ulonglong2 uB = *(const ulonglong2*)&U[k * 8 + 4];
                    fma2(ah0, uA.x, w2); fma2(ah1, uA.y, w2);
                    fma2(ah2, uB.x, w2); fma2(ah3, uB.y, w2);
                }
            }
            // bias in reference order: gi = dot+bih; gh = dot+bhh
            unsigned long long bi2 = pack2(bi), bh2 = pack2(bh);
            if (g < 2) {
                // r,z gates: store s = (gi) + (gh)  [sigmoid arg]
                float* gp = G + g * 800 + iu * 8;
                st2(gp + 0, add2(add2(ai0, bi2), add2(ah0, bh2)));
                st2(gp + 2, add2(add2(ai1, bi2), add2(ah1, bh2)));
                st2(gp + 4, add2(add2(ai2, bi2), add2(ah2, bh2)));
                st2(gp + 6, add2(add2(ai3, bi2), add2(ah3, bh2)));
            } else {
                // n gate: store gin and ghn separately
                float* gip = G + 1600 + iu * 8;
                st2(gip + 0, add2(ai0, bi2));
                st2(gip + 2, add2(ai1, bi2));
                st2(gip + 4, add2(ai2, bi2));
                st2(gip + 6, add2(ai3, bi2));
                float* ghp = G + 2400 + iu * 8;
                st2(ghp + 0, add2(ah0, bh2));
                st2(ghp + 2, add2(ah1, bh2));
                st2(ghp + 4, add2(ah2, bh2));
                st2(ghp + 6, add2(ah3, bh2));
            }
        }
        __syncthreads();   // G ready; all U reads of this step done

        // stage next input into U x-part
        if (t + 1 < T) {
#pragma unroll
            for (int p = 0; p < NPF; p++) {
                int idx = tid + p * 320;
                if (idx < KIN * 8) {
                    int r = idx / KIN, k = idx - r * KIN;
                    U[k * 8 + r] = nx[p];
                }
            }
        }

        // combine: 800 (row,unit) items over 320 threads, coalesced in iu
        for (int item = tid; item < H * 8; item += 320) {
            int r = item / H, iu2 = item - r * H;
            float sr  = G[iu2 * 8 + r];
            float sz  = G[800 + iu2 * 8 + r];
            float gin = G[1600 + iu2 * 8 + r];
            float ghn = G[2400 + iu2 * 8 + r];
            float hold = U[(KIN + iu2) * 8 + r];
            float rr = sigf(sr);
            float zz = sigf(sz);
            float nn = tanhf(__fadd_rn(gin, __fmul_rn(rr, ghn)));
            float t1 = __fmul_rn(__fadd_rn(1.0f, -zz), nn);
            float t2 = __fmul_rn(zz, hold);
            float hn = __fadd_rn(t1, t2);
            U[(KIN + iu2) * 8 + r] = hn;
            int b = b0 + r;
            if (ys) ys[((size_t)t * B + b) * H + iu2] = hn;
            if (hT && t == T - 1) hT[(size_t)b * H + iu2] = hn;
        }
        __syncthreads();   // U (x and h) updated for next step
    }
}

// target is int32 on device (harness downcasts int64 inputs to int32).
__global__ void gather_emb_kernel(const int* __restrict__ target,
                                  const float* __restrict__ emb,
                                  float* __restrict__ out)
{
    int idx = blockIdx.x * blockDim.x + threadIdx.x;
    const int N = PP * BB * EE;
    if (idx >= N) return;
    int row = idx / EE;
    int e = idx - row * EE;
    int t = __ldg(&target[row]);
    t = min(max(t, 0), DD - 1);   // crash-insurance clamp
    out[idx] = __ldg(&emb[t * EE + e]);
}

// logits [79,1024,64] + first-max argmax + target_cal copy.
// One warp per row; lane computes columns (lane, lane+32).
// k-ordered FMA dot from 0, bias added at the end (reference op order).
__global__ void __launch_bounds__(256)
logits_kernel(const float* __restrict__ d1, const float* __restrict__ W,
              const float* __restrict__ bias, const int* __restrict__ tgt,
              float* __restrict__ out_sm, float* __restrict__ out_tc,
              float* __restrict__ out_am)
{
    const int ROWS = (PP - 1) * BB;
    __shared__ float WT[HH * DD]; // WT[k*64+j] = W[j*100+k]
    int tid = threadIdx.x;
    for (int idx = tid; idx < HH * DD; idx += 256) {
        int k = idx >> 6, j = idx & 63;
        WT[idx] = W[j * HH + k];
    }
    __syncthreads();
    int warp = tid >> 5, lane = tid & 31;
    float b0 = __ldg(&bias[lane]), b1 = __ldg(&bias[lane + 32]);
    for (int row = blockIdx.x * 8 + warp; row < ROWS; row += gridDim.x * 8) {
        const float* h = d1 + (size_t)row * HH;
        float a0 = 0.f, a1 = 0.f;
#pragma unroll 4
        for (int k = 0; k < HH; k++) {
            float hk = __ldg(&h[k]);
            a0 = fmaf(hk, WT[k * 64 + lane], a0);
            a1 = fmaf(hk, WT[k * 64 + lane + 32], a1);
        }
        a0 = __fadd_rn(a0, b0);
        a1 = __fadd_rn(a1, b1);
        if (out_sm) {
            out_sm[(size_t)row * 64 + lane] = a0;
            out_sm[(size_t)row * 64 + lane + 32] = a1;
        }
        float v; int bi;
        if (a1 > a0) { v = a1; bi = lane + 32; } else { v = a0; bi = lane; }
#pragma unroll
        for (int off = 16; off > 0; off >>= 1) {
            float ov = __shfl_down_sync(0xFFFFFFFFu, v, off);
            int oi = __shfl_down_sync(0xFFFFFFFFu, bi, off);
            if (ov > v || (ov == v && oi < bi)) { v = ov; bi = oi; }
        }
        if (lane == 0) {
            if (out_am) out_am[row] = (float)bi;
            if (out_tc) out_tc[row] = (float)__ldg(&tgt[BB + row]);
        }
    }
}

extern "C" void kernel_launch(void* const* d_in, const int* in_sizes, int n_in,
                              void* d_out, int out_size)
{
    const float* x = (const float*)d_in[0];
    const int* target = (const int*)d_in[1];
    const float* emb = (const float*)d_in[2];
    const float* eW0 = (const float*)d_in[3];
    const float* eU0 = (const float*)d_in[4];
    const float* ebi0 = (const float*)d_in[5];
    const float* ebh0 = (const float*)d_in[6];
    const float* eW1 = (const float*)d_in[7];
    const float* eU1 = (const float*)d_in[8];
    const float* ebi1 = (const float*)d_in[9];
    const float* ebh1 = (const float*)d_in[10];
    const float* dW0 = (const float*)d_in[11];
    const float* dU0 = (const float*)d_in[12];
    const float* dbi0 = (const float*)d_in[13];
    const float* dbh0 = (const float*)d_in[14];
    const float* dW1 = (const float*)d_in[15];
    const float* dU1 = (const float*)d_in[16];
    const float* dbi1 = (const float*)d_in[17];
    const float* dbh1 = (const float*)d_in[18];
    const float* linW = (const float*)d_in[19];
    const float* linb = (const float*)d_in[20];

    float *e0, *d0, *d1, *decin, *h0, *h1;
    cudaGetSymbolAddress((void**)&e0, g_e0);
    cudaGetSymbolAddress((void**)&d0, g_d0);
    cudaGetSymbolAddress((void**)&d1, g_d1);
    cudaGetSymbolAddress((void**)&decin, g_decin);
    cudaGetSymbolAddress((void**)&h0, g_henc0);
    cudaGetSymbolAddress((void**)&h1, g_henc1);

    // smem: Wt KS*300 + U KTOT*8 + G 3200 floats
    const int SMEM26  = (126 * 300 + 126 * 8 + 3200) * 4;  // 168,032
    const int SMEM100 = (177 * 300 + 200 * 8 + 3200) * 4;  // 231,600
    cudaFuncSetAttribute(gru_kernel<EE, 0>,
        cudaFuncAttributeMaxDynamicSharedMemorySize, SMEM26);
    cudaFuncSetAttribute(gru_kernel<HH, 23>,
        cudaFuncAttributeMaxDynamicSharedMemorySize, SMEM100);

    const int GRID = BB / 8; // 128 CTAs x 8 batch rows

    // encoder layer 0: x -> e0, hT -> g_henc0
    gru_kernel<EE, 0><<<GRID, 320, SMEM26>>>(TT, x, eW0, eU0, ebi0, ebh0,
                                             nullptr, e0, h0);
    // encoder layer 1: e0 -> (discard ys), hT -> g_henc1
    gru_kernel<HH, 23><<<GRID, 320, SMEM100>>>(TT, e0, eW1, eU1, ebi1, ebh1,
                                               nullptr, nullptr, h1);
    // decoder input gather
    {
        int N = PP * BB * EE;
        gather_emb_kernel<<<(N + 255) / 256, 256>>>(target, emb, decin);
    }
    // decoder layer 0: decin -> d0, h0 = g_henc0
    gru_kernel<EE, 0><<<GRID, 320, SMEM26>>>(PP, decin, dW0, dU0, dbi0, dbh0,
                                             h0, d0, nullptr);
    // decoder layer 1: d0 -> d1, h0 = g_henc1
    gru_kernel<HH, 23><<<GRID, 320, SMEM100>>>(PP, d0, dW1, dU1, dbi1, dbh1,
                                               h1, d1, nullptr);
    // epilogue: logits + argmax + target_cal, packed into d_out as float32
    {
        float* out = (float*)d_out;
        float* out_sm = (out_size >= (int)SM_N) ? out : nullptr;
        float* out_tc = (out_size >= (int)(SM_N + TG_N)) ? out + SM_N : nullptr;
        float* out_am = (out_size >= (int)(SM_N + 2 * TG_N)) ? out + SM_N + TG_N : nullptr;
        logits_kernel<<<1184, 256>>>(d1, linW, linb, target, out_sm, out_tc, out_am);
    }
}

// round 13
// speedup vs baseline: 1.2229x; 1.0316x over previous
#include <cuda_runtime.h>
#include <cuda_bf16.h>

#define TT 500
#define BB 1024
#define EE 26
#define HH 100
#define PP 80
#define DD 64

static const long long SM_N = (long long)(PP - 1) * BB * DD; // 5177344
static const long long TG_N = (long long)(PP - 1) * BB;      // 80896

// static device scratch (no allocation allowed)
__device__ float g_e0[TT * BB * HH];
__device__ float g_d0[PP * BB * HH];
__device__ float g_d1[PP * BB * HH];
__device__ float g_decin[PP * BB * EE];
__device__ float g_henc0[BB * HH];
__device__ float g_henc1[BB * HH];

__device__ __forceinline__ float sigf(float x) {
    return 1.0f / (1.0f + expf(-x));
}

// ---- packed f32x2 helpers (each half = independent IEEE op -> bitwise
// identical to scalar fmaf/__fadd_rn per lane) ----
__device__ __forceinline__ unsigned long long pack2(float w) {
    unsigned long long r;
    asm("mov.b64 %0, {%1, %1};" : "=l"(r) : "f"(w));
    return r;
}
__device__ __forceinline__ void fma2(unsigned long long& a,
                                     unsigned long long u,
                                     unsigned long long w) {
    asm("fma.rn.f32x2 %0, %1, %2, %0;" : "+l"(a) : "l"(u), "l"(w));
}
__device__ __forceinline__ unsigned long long add2(unsigned long long a,
                                                   unsigned long long b) {
    unsigned long long r;
    asm("add.rn.f32x2 %0, %1, %2;" : "=l"(r) : "l"(a), "l"(b));
    return r;
}
__device__ __forceinline__ void st2(float* p, unsigned long long v) {
    union { unsigned long long u; float2 f; } c;
    c.u = v;
    *(float2*)p = c.f;
}

// Persistent GRU layer, gi/gh split-thread version.
// 640 threads: tid 0..299 own the INPUT-part dot (gi) of gate-row j = tid;
// tid 320..619 own the HIDDEN-part dot (gh) of j = tid-320. Both chains are
// the reference's own separate accumulators (ascending-k FMA, bias after
// dot); the combine applies __fadd_rn(gi, gh) and the unfused elementwise
// ops in exactly the reference order -> trajectory is bitwise identical to
// the R11/R12 passing kernels.
// Smem: Wt_i[(KIN-SI)][300], Wt_h[(100-SH)][300], U[KTOT][8], G[6][100][8].
// Tails of each weight row (SI / SH k's) live in per-thread registers.
template <int KIN, int SI, int SH>
__global__ void __launch_bounds__(640, 1)
gru_kernel(int T,
           const float* __restrict__ in,   // [T,B,KIN]
           const float* __restrict__ Wih,  // [300,KIN]
           const float* __restrict__ Whh,  // [300,100]
           const float* __restrict__ bih,
           const float* __restrict__ bhh,
           const float* __restrict__ h0,   // [B,100] or null (zeros)
           float* __restrict__ ys,         // [T,B,100] or null
           float* __restrict__ hT)         // [B,100] or null
{
    constexpr int H = HH, J = 3 * HH, B = BB, R = 8;
    constexpr int KTOT = KIN + H;
    constexpr int KI_S = KIN - SI;       // input k-rows in smem
    constexpr int KH_S = H - SH;         // hidden k-rows in smem
    constexpr int NPF = (KIN * 8 + 639) / 640;
    constexpr int MAXS = (SI > SH ? SI : SH) > 0 ? (SI > SH ? SI : SH) : 1;
    extern __shared__ float sm[];
    float* Wt_i = sm;                    // KI_S * 300
    float* Wt_h = Wt_i + KI_S * 300;     // KH_S * 300
    float* U    = Wt_h + KH_S * 300;     // KTOT * 8
    float* G    = U + KTOT * 8;          // 4800: gi[3][100][8], gh at +2400

    const int tid = threadIdx.x;
    const int b0 = blockIdx.x * R;
    const bool rin = (tid < J);
    const bool rhid = (tid >= 320 && tid < 320 + J);
    const int j = rin ? tid : (rhid ? tid - 320 : 0);
    const int g = j / H;
    const int iu = j - g * H;

    // --- weight transpose into smem ---
    for (int idx = tid; idx < J * KI_S; idx += 640) {
        int jj = idx / KI_S, k = idx - jj * KI_S;
        Wt_i[k * J + jj] = Wih[jj * KIN + k];
    }
    for (int idx = tid; idx < J * KH_S; idx += 640) {
        int jj = idx / KH_S, k = idx - jj * KH_S;
        Wt_h[k * J + jj] = Whh[jj * H + k];
    }
    // --- register weight tails (ascending-k continuation) ---
    float wsp[MAXS];
    if constexpr (SI > 0) {
        if (rin) {
#pragma unroll
            for (int s = 0; s < SI; s++) wsp[s] = Wih[j * KIN + KI_S + s];
        }
    }
    if constexpr (SH > 0) {
        if (rhid) {
#pragma unroll
            for (int s = 0; s < SH; s++) wsp[s] = Whh[j * H + KH_S + s];
        }
    }
    // --- init hidden part of U ---
    for (int idx = tid; idx < H * 8; idx += 640) {
        int ih = idx >> 3, r = idx & 7;
        U[(KIN + ih) * 8 + r] = h0 ? h0[(size_t)(b0 + r) * H + ih] : 0.0f;
    }
    // --- stage x_0 ---
    for (int idx = tid; idx < KIN * 8; idx += 640) {
        int r = idx / KIN, k = idx - r * KIN;
        U[k * 8 + r] = in[(size_t)(b0 + r) * KIN + k];
    }
    float bown = 0.f;
    if (rin) bown = bih[j];
    if (rhid) bown = bhh[j];
    __syncthreads();

    for (int t = 0; t < T; ++t) {
        // prefetch next step's input (hidden under dot phase)
        float nx[NPF];
        if (t + 1 < T) {
            const float* inp = in + (size_t)(t + 1) * B * KIN;
#pragma unroll
            for (int p = 0; p < NPF; p++) {
                int idx = tid + p * 640;
                if (idx < KIN * 8) {
                    int r = idx / KIN, k = idx - r * KIN;
                    nx[p] = inp[(size_t)(b0 + r) * KIN + k];
                }
            }
        }

        if (rin) {
            unsigned long long a0 = 0, a1 = 0, a2 = 0, a3 = 0;
            const float* wcol = Wt_i + j;
#pragma unroll 4
            for (int k = 0; k < KI_S; k++) {
                unsigned long long w2 = pack2(wcol[k * J]);
                ulonglong2 uA = *(const ulonglong2*)&U[k * 8];
                ulonglong2 uB = *(const ulonglong2*)&U[k * 8 + 4];
                fma2(a0, uA.x, w2); fma2(a1, uA.y, w2);
                fma2(a2, uB.x, w2); fma2(a3, uB.y, w2);
            }
            if constexpr (SI > 0) {
#pragma unroll
                for (int s = 0; s < SI; s++) {
                    int k = KI_S + s;
                    unsigned long long w2 = pack2(wsp[s]);
                    ulonglong2 uA = *(const ulonglong2*)&U[k * 8];
                    ulonglong2 uB = *(const ulonglong2*)&U[k * 8 + 4];
                    fma2(a0, uA.x, w2); fma2(a1, uA.y, w2);
                    fma2(a2, uB.x, w2); fma2(a3, uB.y, w2);
                }
            }
            unsigned long long b2 = pack2(bown);
            float* gp = G + g * 800 + iu * 8;          // gi = dot + bih
            st2(gp + 0, add2(a0, b2));
            st2(gp + 2, add2(a1, b2));
            st2(gp + 4, add2(a2, b2));
            st2(gp + 6, add2(a3, b2));
        } else if (rhid) {
            unsigned long long a0 = 0, a1 = 0, a2 = 0, a3 = 0;
            const float* wcol = Wt_h + j;
#pragma unroll 4
            for (int k = 0; k < KH_S; k++) {
                unsigned long long w2 = pack2(wcol[k * J]);
                ulonglong2 uA = *(const ulonglong2*)&U[(KIN + k) * 8];
                ulonglong2 uB = *(const ulonglong2*)&U[(KIN + k) * 8 + 4];
                fma2(a0, uA.x, w2); fma2(a1, uA.y, w2);
                fma2(a2, uB.x, w2); fma2(a3, uB.y, w2);
            }
            if constexpr (SH > 0) {
#pragma unroll
                for (int s = 0; s < SH; s++) {
                    int k = KIN + KH_S + s;
                    unsigned long long w2 = pack2(wsp[s]);
                    ulonglong2 uA = *(const ulonglong2*)&U[k * 8];
                    ulonglong2 uB = *(const ulonglong2*)&U[k * 8 + 4];
                    fma2(a0, uA.x, w2); fma2(a1, uA.y, w2);
                    fma2(a2, uB.x, w2); fma2(a3, uB.y, w2);
                }
            }
            unsigned long long b2 = pack2(bown);
            float* gp = G + 2400 + g * 800 + iu * 8;   // gh = dot + bhh
            st2(gp + 0, add2(a0, b2));
            st2(gp + 2, add2(a1, b2));
            st2(gp + 4, add2(a2, b2));
            st2(gp + 6, add2(a3, b2));
        }
        __syncthreads();   // G ready; all U reads of this step done

        // stage next input into U x-part
        if (t + 1 < T) {
#pragma unroll
            for (int p = 0; p < NPF; p++) {
                int idx = tid + p * 640;
                if (idx < KIN * 8) {
                    int r = idx / KIN, k = idx - r * KIN;
                    U[k * 8 + r] = nx[p];
                }
            }
        }

        // combine: 800 (row,unit) items over 640 threads
        for (int item = tid; item < H * 8; item += 640) {
            int r = item / H, iu2 = item - r * H;
            float gir = G[iu2 * 8 + r];
            float ghr = G[2400 + iu2 * 8 + r];
            float giz = G[800 + iu2 * 8 + r];
            float ghz = G[2400 + 800 + iu2 * 8 + r];
            float gin = G[1600 + iu2 * 8 + r];
            float ghn = G[2400 + 1600 + iu2 * 8 + r];
            float hold = U[(KIN + iu2) * 8 + r];
            float rr = sigf(__fadd_rn(gir, ghr));
            float zz = sigf(__fadd_rn(giz, ghz));
            float nn = tanhf(__fadd_rn(gin, __fmul_rn(rr, ghn)));
            float t1 = __fmul_rn(__fadd_rn(1.0f, -zz), nn);
            float t2 = __fmul_rn(zz, hold);
            float hn = __fadd_rn(t1, t2);
            U[(KIN + iu2) * 8 + r] = hn;
            int b = b0 + r;
            if (ys) ys[((size_t)t * B + b) * H + iu2] = hn;
            if (hT && t == T - 1) hT[(size_t)b * H + iu2] = hn;
        }
        __syncthreads();   // U (x and h) updated for next step
    }
}

// target is int32 on device (harness downcasts int64 inputs to int32).
__global__ void gather_emb_kernel(const int* __restrict__ target,
                                  const float* __restrict__ emb,
                                  float* __restrict__ out)
{
    int idx = blockIdx.x * blockDim.x + threadIdx.x;
    const int N = PP * BB * EE;
    if (idx >= N) return;
    int row = idx / EE;
    int e = idx - row * EE;
    int t = __ldg(&target[row]);
    t = min(max(t, 0), DD - 1);   // crash-insurance clamp
    out[idx] = __ldg(&emb[t * EE + e]);
}

// logits [79,1024,64] + first-max argmax + target_cal copy.
// One warp per row; lane computes columns (lane, lane+32).
// k-ordered FMA dot from 0, bias added at the end (reference op order).
__global__ void __launch_bounds__(256)
logits_kernel(const float* __restrict__ d1, const float* __restrict__ W,
              const float* __restrict__ bias, const int* __restrict__ tgt,
              float* __restrict__ out_sm, float* __restrict__ out_tc,
              float* __restrict__ out_am)
{
    const int ROWS = (PP - 1) * BB;
    __shared__ float WT[HH * DD]; // WT[k*64+j] = W[j*100+k]
    int tid = threadIdx.x;
    for (int idx = tid; idx < HH * DD; idx += 256) {
        int k = idx >> 6, j = idx & 63;
        WT[idx] = W[j * HH + k];
    }
    __syncthreads();
    int warp = tid >> 5, lane = tid & 31;
    float b0 = __ldg(&bias[lane]), b1 = __ldg(&bias[lane + 32]);
    for (int row = blockIdx.x * 8 + warp; row < ROWS; row += gridDim.x * 8) {
        const float* h = d1 + (size_t)row * HH;
        float a0 = 0.f, a1 = 0.f;
#pragma unroll 4
        for (int k = 0; k < HH; k++) {
            float hk = __ldg(&h[k]);
            a0 = fmaf(hk, WT[k * 64 + lane], a0);
            a1 = fmaf(hk, WT[k * 64 + lane + 32], a1);
        }
        a0 = __fadd_rn(a0, b0);
        a1 = __fadd_rn(a1, b1);
        if (out_sm) {
            out_sm[(size_t)row * 64 + lane] = a0;
            out_sm[(size_t)row * 64 + lane + 32] = a1;
        }
        float v; int bi;
        if (a1 > a0) { v = a1; bi = lane + 32; } else { v = a0; bi = lane; }
#pragma unroll
        for (int off = 16; off > 0; off >>= 1) {
            float ov = __shfl_down_sync(0xFFFFFFFFu, v, off);
            int oi = __shfl_down_sync(0xFFFFFFFFu, bi, off);
            if (ov > v || (ov == v && oi < bi)) { v = ov; bi = oi; }
        }
        if (lane == 0) {
            if (out_am) out_am[row] = (float)bi;
            if (out_tc) out_tc[row] = (float)__ldg(&tgt[BB + row]);
        }
    }
}

extern "C" void kernel_launch(void* const* d_in, const int* in_sizes, int n_in,
                              void* d_out, int out_size)
{
    const float* x = (const float*)d_in[0];
    const int* target = (const int*)d_in[1];
    const float* emb = (const float*)d_in[2];
    const float* eW0 = (const float*)d_in[3];
    const float* eU0 = (const float*)d_in[4];
    const float* ebi0 = (const float*)d_in[5];
    const float* ebh0 = (const float*)d_in[6];
    const float* eW1 = (const float*)d_in[7];
    const float* eU1 = (const float*)d_in[8];
    const float* ebi1 = (const float*)d_in[9];
    const float* ebh1 = (const float*)d_in[10];
    const float* dW0 = (const float*)d_in[11];
    const float* dU0 = (const float*)d_in[12];
    const float* dbi0 = (const float*)d_in[13];
    const float* dbh0 = (const float*)d_in[14];
    const float* dW1 = (const float*)d_in[15];
    const float* dU1 = (const float*)d_in[16];
    const float* dbi1 = (const float*)d_in[17];
    const float* dbh1 = (const float*)d_in[18];
    const float* linW = (const float*)d_in[19];
    const float* linb = (const float*)d_in[20];

    float *e0, *d0, *d1, *decin, *h0, *h1;
    cudaGetSymbolAddress((void**)&e0, g_e0);
    cudaGetSymbolAddress((void**)&d0, g_d0);
    cudaGetSymbolAddress((void**)&d1, g_d1);
    cudaGetSymbolAddress((void**)&decin, g_decin);
    cudaGetSymbolAddress((void**)&h0, g_henc0);
    cudaGetSymbolAddress((void**)&h1, g_henc1);

    // smem floats: Wt_i + Wt_h + U + G
    const int SMEM26  = (26 * 300 + 86 * 300 + 126 * 8 + 4800) * 4;  // 157,632
    const int SMEM100 = (86 * 300 + 86 * 300 + 200 * 8 + 4800) * 4;  // 232,000
    cudaFuncSetAttribute(gru_kernel<EE, 0, 14>,
        cudaFuncAttributeMaxDynamicSharedMemorySize, SMEM26);
    cudaFuncSetAttribute(gru_kernel<HH, 14, 14>,
        cudaFuncAttributeMaxDynamicSharedMemorySize, SMEM100);

    const int GRID = BB / 8; // 128 CTAs x 8 batch rows

    // encoder layer 0: x -> e0, hT -> g_henc0
    gru_kernel<EE, 0, 14><<<GRID, 640, SMEM26>>>(TT, x, eW0, eU0, ebi0, ebh0,
                                                 nullptr, e0, h0);
    // encoder layer 1: e0 -> (discard ys), hT -> g_henc1
    gru_kernel<HH, 14, 14><<<GRID, 640, SMEM100>>>(TT, e0, eW1, eU1, ebi1, ebh1,
                                                   nullptr, nullptr, h1);
    // decoder input gather
    {
        int N = PP * BB * EE;
        gather_emb_kernel<<<(N + 255) / 256, 256>>>(target, emb, decin);
    }
    // decoder layer 0: decin -> d0, h0 = g_henc0
    gru_kernel<EE, 0, 14><<<GRID, 640, SMEM26>>>(PP, decin, dW0, dU0, dbi0, dbh0,
                                                 h0, d0, nullptr);
    // decoder layer 1: d0 -> d1, h0 = g_henc1
    gru_kernel<HH, 14, 14><<<GRID, 640, SMEM100>>>(PP, d0, dW1, dU1, dbi1, dbh1,
                                                   h1, d1, nullptr);
    // epilogue: logits + argmax + target_cal, packed into d_out as float32
    {
        float* out = (float*)d_out;
        float* out_sm = (out_size >= (int)SM_N) ? out : nullptr;
        float* out_tc = (out_size >= (int)(SM_N + TG_N)) ? out + SM_N : nullptr;
        float* out_am = (out_size >= (int)(SM_N + 2 * TG_N)) ? out + SM_N + TG_N : nullptr;
        logits_kernel<<<1184, 256>>>(d1, linW, linb, target, out_sm, out_tc, out_am);
    }
}

// round 14
// speedup vs baseline: 1.3255x; 1.0839x over previous
#include <cuda_runtime.h>
#include <cuda_bf16.h>

#define TT 500
#define BB 1024
#define EE 26
#define HH 100
#define PP 80
#define DD 64

static const long long SM_N = (long long)(PP - 1) * BB * DD; // 5177344
static const long long TG_N = (long long)(PP - 1) * BB;      // 80896

// static device scratch (no allocation allowed)
__device__ float g_e0[TT * BB * HH];
__device__ float g_d0[PP * BB * HH];
__device__ float g_d1[PP * BB * HH];
__device__ float g_decin[PP * BB * EE];
__device__ float g_henc0[BB * HH];
__device__ float g_henc1[BB * HH];
__device__ float g_gi[(size_t)TT * BB * 300];   // gi buffer, reused per layer

__device__ __forceinline__ float sigf(float x) {
    return 1.0f / (1.0f + expf(-x));
}

// ---- packed f32x2 helpers (each half = independent IEEE op -> bitwise
// identical to scalar fmaf/__fadd_rn per lane) ----
__device__ __forceinline__ unsigned long long pack2(float w) {
    unsigned long long r;
    asm("mov.b64 %0, {%1, %1};" : "=l"(r) : "f"(w));
    return r;
}
__device__ __forceinline__ void fma2(unsigned long long& a,
                                     unsigned long long u,
                                     unsigned long long w) {
    asm("fma.rn.f32x2 %0, %1, %2, %0;" : "+l"(a) : "l"(u), "l"(w));
}
__device__ __forceinline__ unsigned long long add2(unsigned long long a,
                                                   unsigned long long b) {
    unsigned long long r;
    asm("add.rn.f32x2 %0, %1, %2;" : "=l"(r) : "l"(a), "l"(b));
    return r;
}
__device__ __forceinline__ void unpack2(unsigned long long v, float& lo, float& hi) {
    asm("mov.b64 {%0, %1}, %2;" : "=f"(lo), "=f"(hi) : "l"(v));
}

// ============================================================================
// gi GEMM: Gi[rows,300] = X[rows,K] @ Wih^T + bih
// Persistent CTAs; weights in smem once; register tile 4 cols x 8 rows.
// Per-output chain: ascending-k FMA from 0, bias added after -> bitwise
// identical to the input-part chain of the passing R13 kernel.
// ============================================================================
template <int K>
__global__ void __launch_bounds__(640, 1)
gemm_gi(int ntiles,
        const float* __restrict__ X,    // [rows, K]
        const float* __restrict__ Wih,  // [300, K]
        const float* __restrict__ bih,  // [300]
        float* __restrict__ Gi)         // [rows, 300]
{
    constexpr int XS = 68;              // padded tile row stride (floats)
    extern __shared__ float sm[];
    float* Wt = sm;                     // K*300, Wt[k*300+j] = Wih[j*K+k]
    float* Bs = Wt + K * 300;           // 300 (+4 pad)
    float* Xs = Bs + 304;               // K*68, Xs[k*68+row]

    const int tid = threadIdx.x;
    for (int idx = tid; idx < 300 * K; idx += 640) {
        int j = idx / K, k = idx - j * K;
        Wt[k * 300 + j] = Wih[idx];
    }
    if (tid < 300) Bs[tid] = bih[tid];
    __syncthreads();

    const int cg = tid % 75;            // col group: cols 4cg..4cg+3
    const int rg = tid / 75;            // row group: rows 8rg..8rg+7

    for (int tile = blockIdx.x; tile < ntiles; tile += gridDim.x) {
        const float* xsrc = X + (size_t)tile * 64 * K;
        for (int idx = tid; idx < 64 * K; idx += 640) {
            int row = idx / K, k = idx - row * K;
            Xs[k * XS + row] = xsrc[idx];
        }
        __syncthreads();
        if (tid < 600) {
            unsigned long long acc[4][4];
#pragma unroll
            for (int c = 0; c < 4; c++)
#pragma unroll
                for (int p = 0; p < 4; p++) acc[c][p] = 0ULL;
#pragma unroll 2
            for (int k = 0; k < K; k++) {
                float4 w4 = *(const float4*)&Wt[k * 300 + cg * 4];
                ulonglong2 xa = *(const ulonglong2*)&Xs[k * XS + rg * 8];
                ulonglong2 xb = *(const ulonglong2*)&Xs[k * XS + rg * 8 + 4];
                unsigned long long w2;
                w2 = pack2(w4.x);
                fma2(acc[0][0], xa.x, w2); fma2(acc[0][1], xa.y, w2);
                fma2(acc[0][2], xb.x, w2); fma2(acc[0][3], xb.y, w2);
                w2 = pack2(w4.y);
                fma2(acc[1][0], xa.x, w2); fma2(acc[1][1], xa.y, w2);
                fma2(acc[1][2], xb.x, w2); fma2(acc[1][3], xb.y, w2);
                w2 = pack2(w4.z);
                fma2(acc[2][0], xa.x, w2); fma2(acc[2][1], xa.y, w2);
                fma2(acc[2][2], xb.x, w2); fma2(acc[2][3], xb.y, w2);
                w2 = pack2(w4.w);
                fma2(acc[3][0], xa.x, w2); fma2(acc[3][1], xa.y, w2);
                fma2(acc[3][2], xb.x, w2); fma2(acc[3][3], xb.y, w2);
            }
            float b0 = Bs[cg * 4 + 0], b1 = Bs[cg * 4 + 1];
            float b2 = Bs[cg * 4 + 2], b3 = Bs[cg * 4 + 3];
            float* orow = Gi + ((size_t)tile * 64 + rg * 8) * 300 + cg * 4;
#pragma unroll
            for (int p = 0; p < 4; p++) {
                float l0, h0, l1, h1, l2, h2, l3, h3;
                unpack2(acc[0][p], l0, h0);
                unpack2(acc[1][p], l1, h1);
                unpack2(acc[2][p], l2, h2);
                unpack2(acc[3][p], l3, h3);
                float4 v0 = { __fadd_rn(l0, b0), __fadd_rn(l1, b1),
                              __fadd_rn(l2, b2), __fadd_rn(l3, b3) };
                float4 v1 = { __fadd_rn(h0, b0), __fadd_rn(h1, b1),
                              __fadd_rn(h2, b2), __fadd_rn(h3, b3) };
                *(float4*)(orow + (size_t)(2 * p) * 300) = v0;
                *(float4*)(orow + (size_t)(2 * p + 1) * 300) = v1;
            }
        }
        __syncthreads();
    }
}

// ============================================================================
// Recurrent GRU (hidden part only). gi comes precomputed from gmem.
// One CTA owns R=8 batch rows for all T steps. 600 dot threads: interleaved
// (j = tid>>1, rhalf = tid&1); each computes the ascending-k gh chain for
// gate-row j over 4 batch rows, + bhh after. Combine phase applies the
// reference's unfused elementwise ops -> trajectory bitwise identical.
// Smem: Wt[100][300] (120KB), U[100][8] (h state), G[3][8][100] (gh gates).
// ============================================================================
__global__ void __launch_bounds__(640, 1)
gru_rec(int T,
        const float* __restrict__ gi,   // [T,B,300]
        const float* __restrict__ Whh,  // [300,100]
        const float* __restrict__ bhh,  // [300]
        const float* __restrict__ h0,   // [B,100] or null (zeros)
        float* __restrict__ ys,         // [T,B,100] or null
        float* __restrict__ hT)         // [B,100] or null
{
    constexpr int H = HH, J = 300, B = BB;
    extern __shared__ float sm[];
    float* Wt = sm;             // 100*300, Wt[k*300+j] = Whh[j*100+k]
    float* U  = Wt + 30000;     // 100*8, U[ih*8+r]
    float* G  = U + 800;        // 3*800, G[g*800 + r*100 + iu]

    const int tid = threadIdx.x;
    const int b0 = blockIdx.x * 8;
    const bool dot = (tid < 600);
    const int j = tid >> 1;       // 0..299
    const int rh = tid & 1;       // row half
    const int g = j / H;
    const int iu = j - g * H;
    const float bown = dot ? bhh[j] : 0.f;

    for (int idx = tid; idx < J * H; idx += 640) {
        int jj = idx / H, k = idx - jj * H;
        Wt[k * 300 + jj] = Whh[idx];
    }
    for (int idx = tid; idx < H * 8; idx += 640) {
        int ih = idx >> 3, r = idx & 7;
        U[idx] = h0 ? h0[(size_t)(b0 + r) * H + ih] : 0.0f;
    }
    // combine item mapping (item = r*100 + iu2): thread owns tid, tid+640
    const int r0 = tid / 100, q0 = tid - r0 * 100;
    const int it1 = tid + 640;
    const int r1 = it1 / 100, q1 = it1 - r1 * 100;
    const bool has1 = (it1 < 800);
    __syncthreads();

    for (int t = 0; t < T; ++t) {
        // prefetch this step's gi for the combine items (hidden under dot)
        const float* gp = gi + ((size_t)t * B + b0) * 300;
        float p00 = gp[(size_t)r0 * 300 + q0];
        float p01 = gp[(size_t)r0 * 300 + 100 + q0];
        float p02 = gp[(size_t)r0 * 300 + 200 + q0];
        float p10 = 0.f, p11 = 0.f, p12 = 0.f;
        if (has1) {
            p10 = gp[(size_t)r1 * 300 + q1];
            p11 = gp[(size_t)r1 * 300 + 100 + q1];
            p12 = gp[(size_t)r1 * 300 + 200 + q1];
        }

        if (dot) {
            unsigned long long a0 = 0, a1 = 0;
            const float* wcol = Wt + j;
            const float* ub = U + rh * 4;
#pragma unroll 4
            for (int k = 0; k < H; k++) {
                unsigned long long w2 = pack2(wcol[k * 300]);
                ulonglong2 u = *(const ulonglong2*)&ub[k * 8];
                fma2(a0, u.x, w2);
                fma2(a1, u.y, w2);
            }
            unsigned long long b2 = pack2(bown);
            a0 = add2(a0, b2);
            a1 = add2(a1, b2);
            float v0, v1, v2, v3;
            unpack2(a0, v0, v1);
            unpack2(a1, v2, v3);
            float* gbase = G + g * 800 + iu + rh * 400;
            gbase[0] = v0;
            gbase[100] = v1;
            gbase[200] = v2;
            gbase[300] = v3;
        }
        __syncthreads();   // G ready; all U reads of this step done

        // combine item 0
        {
            float ghr = G[r0 * 100 + q0];
            float ghz = G[800 + r0 * 100 + q0];
            float ghn = G[1600 + r0 * 100 + q0];
            float hold = U[q0 * 8 + r0];
            float rg_ = sigf(__fadd_rn(p00, ghr));
            float zg = sigf(__fadd_rn(p01, ghz));
            float nn = tanhf(__fadd_rn(p02, __fmul_rn(rg_, ghn)));
            float t1 = __fmul_rn(__fadd_rn(1.0f, -zg), nn);
            float t2 = __fmul_rn(zg, hold);
            float hn = __fadd_rn(t1, t2);
            U[q0 * 8 + r0] = hn;
            if (ys) ys[((size_t)t * B + b0 + r0) * H + q0] = hn;
            if (hT && t == T - 1) hT[(size_t)(b0 + r0) * H + q0] = hn;
        }
        if (has1) {
            float ghr = G[r1 * 100 + q1];
            float ghz = G[800 + r1 * 100 + q1];
            float ghn = G[1600 + r1 * 100 + q1];
            float hold = U[q1 * 8 + r1];
            float rg_ = sigf(__fadd_rn(p10, ghr));
            float zg = sigf(__fadd_rn(p11, ghz));
            float nn = tanhf(__fadd_rn(p12, __fmul_rn(rg_, ghn)));
            float t1 = __fmul_rn(__fadd_rn(1.0f, -zg), nn);
            float t2 = __fmul_rn(zg, hold);
            float hn = __fadd_rn(t1, t2);
            U[q1 * 8 + r1] = hn;
            if (ys) ys[((size_t)t * B + b0 + r1) * H + q1] = hn;
            if (hT && t == T - 1) hT[(size_t)(b0 + r1) * H + q1] = hn;
        }
        __syncthreads();   // U updated for next step
    }
}

// target is int32 on device (harness downcasts int64 inputs to int32).
__global__ void gather_emb_kernel(const int* __restrict__ target,
                                  const float* __restrict__ emb,
                                  float* __restrict__ out)
{
    int idx = blockIdx.x * blockDim.x + threadIdx.x;
    const int N = PP * BB * EE;
    if (idx >= N) return;
    int row = idx / EE;
    int e = idx - row * EE;
    int t = __ldg(&target[row]);
    t = min(max(t, 0), DD - 1);   // crash-insurance clamp
    out[idx] = __ldg(&emb[t * EE + e]);
}

// logits [79,1024,64] + first-max argmax + target_cal copy.
__global__ void __launch_bounds__(256)
logits_kernel(const float* __restrict__ d1, const float* __restrict__ W,
              const float* __restrict__ bias, const int* __restrict__ tgt,
              float* __restrict__ out_sm, float* __restrict__ out_tc,
              float* __restrict__ out_am)
{
    const int ROWS = (PP - 1) * BB;
    __shared__ float WT[HH * DD]; // WT[k*64+j] = W[j*100+k]
    int tid = threadIdx.x;
    for (int idx = tid; idx < HH * DD; idx += 256) {
        int k = idx >> 6, j = idx & 63;
        WT[idx] = W[j * HH + k];
    }
    __syncthreads();
    int warp = tid >> 5, lane = tid & 31;
    float b0 = __ldg(&bias[lane]), b1 = __ldg(&bias[lane + 32]);
    for (int row = blockIdx.x * 8 + warp; row < ROWS; row += gridDim.x * 8) {
        const float* h = d1 + (size_t)row * HH;
        float a0 = 0.f, a1 = 0.f;
#pragma unroll 4
        for (int k = 0; k < HH; k++) {
            float hk = __ldg(&h[k]);
            a0 = fmaf(hk, WT[k * 64 + lane], a0);
            a1 = fmaf(hk, WT[k * 64 + lane + 32], a1);
        }
        a0 = __fadd_rn(a0, b0);
        a1 = __fadd_rn(a1, b1);
        if (out_sm) {
            out_sm[(size_t)row * 64 + lane] = a0;
            out_sm[(size_t)row * 64 + lane + 32] = a1;
        }
        float v; int bi;
        if (a1 > a0) { v = a1; bi = lane + 32; } else { v = a0; bi = lane; }
#pragma unroll
        for (int off = 16; off > 0; off >>= 1) {
            float ov = __shfl_down_sync(0xFFFFFFFFu, v, off);
            int oi = __shfl_down_sync(0xFFFFFFFFu, bi, off);
            if (ov > v || (ov == v && oi < bi)) { v = ov; bi = oi; }
        }
        if (lane == 0) {
            if (out_am) out_am[row] = (float)bi;
            if (out_tc) out_tc[row] = (float)__ldg(&tgt[BB + row]);
        }
    }
}

extern "C" void kernel_launch(void* const* d_in, const int* in_sizes, int n_in,
                              void* d_out, int out_size)
{
    const float* x = (const float*)d_in[0];
    const int* target = (const int*)d_in[1];
    const float* emb = (const float*)d_in[2];
    const float* eW0 = (const float*)d_in[3];
    const float* eU0 = (const float*)d_in[4];
    const float* ebi0 = (const float*)d_in[5];
    const float* ebh0 = (const float*)d_in[6];
    const float* eW1 = (const float*)d_in[7];
    const float* eU1 = (const float*)d_in[8];
    const float* ebi1 = (const float*)d_in[9];
    const float* ebh1 = (const float*)d_in[10];
    const float* dW0 = (const float*)d_in[11];
    const float* dU0 = (const float*)d_in[12];
    const float* dbi0 = (const float*)d_in[13];
    const float* dbh0 = (const float*)d_in[14];
    const float* dW1 = (const float*)d_in[15];
    const float* dU1 = (const float*)d_in[16];
    const float* dbi1 = (const float*)d_in[17];
    const float* dbh1 = (const float*)d_in[18];
    const float* linW = (const float*)d_in[19];
    const float* linb = (const float*)d_in[20];

    float *e0, *d0, *d1, *decin, *h0, *h1, *gi;
    cudaGetSymbolAddress((void**)&e0, g_e0);
    cudaGetSymbolAddress((void**)&d0, g_d0);
    cudaGetSymbolAddress((void**)&d1, g_d1);
    cudaGetSymbolAddress((void**)&decin, g_decin);
    cudaGetSymbolAddress((void**)&h0, g_henc0);
    cudaGetSymbolAddress((void**)&h1, g_henc1);
    cudaGetSymbolAddress((void**)&gi, g_gi);

    const int SMEMG26  = (26 * 300 + 304 + 26 * 68) * 4;    // 39,488
    const int SMEMG100 = (100 * 300 + 304 + 100 * 68) * 4;  // 148,416
    const int SMEMR    = (30000 + 800 + 2400) * 4;          // 132,800
    cudaFuncSetAttribute(gemm_gi<EE>,
        cudaFuncAttributeMaxDynamicSharedMemorySize, SMEMG26);
    cudaFuncSetAttribute(gemm_gi<HH>,
        cudaFuncAttributeMaxDynamicSharedMemorySize, SMEMG100);
    cudaFuncSetAttribute(gru_rec,
        cudaFuncAttributeMaxDynamicSharedMemorySize, SMEMR);

    const int ENC_TILES = TT * BB / 64;  // 8000
    const int DEC_TILES = PP * BB / 64;  // 1280
    const int GRID = BB / 8;             // 128

    // encoder layer 0
    gemm_gi<EE><<<148, 640, SMEMG26>>>(ENC_TILES, x, eW0, ebi0, gi);
    gru_rec<<<GRID, 640, SMEMR>>>(TT, gi, eU0, ebh0, nullptr, e0, h0);
    // encoder layer 1
    gemm_gi<HH><<<148, 640, SMEMG100>>>(ENC_TILES, e0, eW1, ebi1, gi);
    gru_rec<<<GRID, 640, SMEMR>>>(TT, gi, eU1, ebh1, nullptr, nullptr, h1);
    // decoder input gather
    {
        int N = PP * BB * EE;
        gather_emb_kernel<<<(N + 255) / 256, 256>>>(target, emb, decin);
    }
    // decoder layer 0
    gemm_gi<EE><<<148, 640, SMEMG26>>>(DEC_TILES, decin, dW0, dbi0, gi);
    gru_rec<<<GRID, 640, SMEMR>>>(PP, gi, dU0, dbh0, h0, d0, nullptr);
    // decoder layer 1
    gemm_gi<HH><<<148, 640, SMEMG100>>>(DEC_TILES, d0, dW1, dbi1, gi);
    gru_rec<<<GRID, 640, SMEMR>>>(PP, gi, dU1, dbh1, h1, d1, nullptr);
    // epilogue
    {
        float* out = (float*)d_out;
        float* out_sm = (out_size >= (int)SM_N) ? out : nullptr;
        float* out_tc = (out_size >= (int)(SM_N + TG_N)) ? out + SM_N : nullptr;
        float* out_am = (out_size >= (int)(SM_N + 2 * TG_N)) ? out + SM_N + TG_N : nullptr;
        logits_kernel<<<1184, 256>>>(d1, linW, linb, target, out_sm, out_tc, out_am);
    }
}